// round 15
// baseline (speedup 1.0000x reference)
#include <cuda_runtime.h>
#include <cuda_fp16.h>
#include <cstdint>
#include <cstddef>

#define BATCH 4
#define SEQT  2048
#define CIN   1152
#define NE    1024
#define NH    16
#define HD    64
#define ROWS  (BATCH*SEQT)   // 8192

// ---- scratch (no allocations allowed) ----
__device__ __half g_h[(size_t)ROWS * CIN];
__device__ __half g_qkv[(size_t)ROWS * 3 * NE];
__device__ __half g_y[(size_t)ROWS * NE];
__device__ __half g_wta[(size_t)3 * NE * CIN];
__device__ __half g_wtp[(size_t)NE * NE];

__device__ __forceinline__ void mma_f16(float c[4], const uint32_t a[4], const uint32_t b[2]) {
    asm volatile(
        "mma.sync.aligned.m16n8k16.row.col.f32.f16.f16.f32 "
        "{%0,%1,%2,%3}, {%4,%5,%6,%7}, {%8,%9}, {%0,%1,%2,%3};\n"
        : "+f"(c[0]), "+f"(c[1]), "+f"(c[2]), "+f"(c[3])
        : "r"(a[0]), "r"(a[1]), "r"(a[2]), "r"(a[3]), "r"(b[0]), "r"(b[1]));
}

__device__ __forceinline__ uint32_t smem_u32(const void* p) {
    return (uint32_t)__cvta_generic_to_shared(p);
}
#define CP_ASYNC16(dst, src) \
    asm volatile("cp.async.cg.shared.global [%0], [%1], 16;\n" :: "r"(dst), "l"(src))
#define CP_COMMIT() asm volatile("cp.async.commit_group;\n")
#define CP_WAIT1()  asm volatile("cp.async.wait_group 1;\n")
#define CP_WAIT0()  asm volatile("cp.async.wait_group 0;\n")
#define LDSM_X4(r0, r1, r2, r3, addr) \
    asm volatile("ldmatrix.sync.aligned.m8n8.x4.shared.b16 {%0,%1,%2,%3}, [%4];" \
                 : "=r"(r0), "=r"(r1), "=r"(r2), "=r"(r3) : "r"(addr))
#define LDSM_X4_T(r0, r1, r2, r3, addr) \
    asm volatile("ldmatrix.sync.aligned.m8n8.x4.trans.shared.b16 {%0,%1,%2,%3}, [%4];" \
                 : "=r"(r0), "=r"(r1), "=r"(r2), "=r"(r3) : "r"(addr))

// ---------------- weight transpose + half convert ----------------
__global__ void transpose_w(const float* __restrict__ W, __half* __restrict__ wT, int K, int N) {
    __shared__ float t[32][33];
    int n0 = blockIdx.x * 32, k0 = blockIdx.y * 32;
    #pragma unroll
    for (int i = threadIdx.y; i < 32; i += 8)
        t[i][threadIdx.x] = W[(size_t)(k0 + i) * N + n0 + threadIdx.x];
    __syncthreads();
    #pragma unroll
    for (int i = threadIdx.y; i < 32; i += 8)
        wT[(size_t)(n0 + i) * K + k0 + threadIdx.x] = __float2half_rn(t[threadIdx.x][i]);
}

// ------------------------- LayerNorm -------------------------
__global__ void ln_kernel(const float* __restrict__ x, const float* __restrict__ w,
                          const float* __restrict__ bb, __half* __restrict__ h) {
    int row = blockIdx.x;
    const float2* xr = (const float2*)(x + (size_t)row * CIN);
    float s1 = 0.f, s2 = 0.f;
    for (int i = threadIdx.x; i < CIN / 2; i += 256) {
        float2 v = xr[i];
        s1 += v.x + v.y; s2 += v.x * v.x + v.y * v.y;
    }
    #pragma unroll
    for (int o = 16; o; o >>= 1) {
        s1 += __shfl_xor_sync(0xffffffffu, s1, o);
        s2 += __shfl_xor_sync(0xffffffffu, s2, o);
    }
    __shared__ float sh1[8], sh2[8];
    int wid = threadIdx.x >> 5, lane = threadIdx.x & 31;
    if (lane == 0) { sh1[wid] = s1; sh2[wid] = s2; }
    __syncthreads();
    float S1 = 0.f, S2 = 0.f;
    #pragma unroll
    for (int i = 0; i < 8; i++) { S1 += sh1[i]; S2 += sh2[i]; }
    float mean = S1 * (1.f / CIN);
    float var  = S2 * (1.f / CIN) - mean * mean;
    float inv  = rsqrtf(var + 1e-5f);
    const float2* w2 = (const float2*)w;
    const float2* b2 = (const float2*)bb;
    __half2* hr = (__half2*)(h + (size_t)row * CIN);
    for (int i = threadIdx.x; i < CIN / 2; i += 256) {
        float2 v = xr[i], ww = w2[i], bz = b2[i];
        hr[i] = __floats2half2_rn((v.x - mean) * inv * ww.x + bz.x,
                                  (v.y - mean) * inv * ww.y + bz.y);
    }
}

// ------------------------- fp16 GEMM: C = A@Bt^T + bias -------------------------
// BK=64, 2-stage cp.async double buffer, 1 sync per 64-K. Each 64-col tile is
// two 32-col slabs at row offsets 0/40 (same bank geometry as validated layout).
template<bool HALF_OUT>
__global__ __launch_bounds__(256) void gemm_f16(
        const __half* __restrict__ A, const __half* __restrict__ Bt,
        const float* __restrict__ bias, void* __restrict__ Cv,
        int M, int N, int K) {
    __shared__ __half As[2][128][80];
    __shared__ __half Bs[2][128][80];
    int tid = threadIdx.x;
    int lane = tid & 31, wid = tid >> 5;
    int wm = (wid & 3) * 32, wn = (wid >> 2) * 64;
    int bm = blockIdx.y * 128, bn = blockIdx.x * 128;
    int g = lane >> 2, tg = lane & 3;

    float acc[2][8][4];
    #pragma unroll
    for (int mt = 0; mt < 2; mt++)
        #pragma unroll
        for (int nt = 0; nt < 8; nt++)
            #pragma unroll
            for (int i = 0; i < 4; i++) acc[mt][nt][i] = 0.f;

    const __half* Abase = A + (size_t)bm * K;
    const __half* Bbase = Bt + (size_t)bn * K;
    int ktiles = K >> 6;                       // 64-K tiles

    int a_row = (lane & 7) + ((lane >> 3) & 1) * 8;
    int a_col = (lane >> 4) * 8;               // within-slab fragment col (+0/8)
    int b_row = (lane & 7) + (lane >> 4) * 8;
    int b_col = ((lane >> 3) & 1) * 8;

    // loader: 1024 16B-chunks per array per tile; gmem col c=(idx&7)*8 maps to
    // smem col (c>>5)*40 + (c&31)
    int lrr = tid >> 3;                        // rows 0..31 (+32*i)
    int lgc = (tid & 7) * 8;                   // gmem col 0..56
    int lsc = (lgc >> 5) * 40 + (lgc & 31);    // smem col

    // prologue: tile 0 -> stage 0
    #pragma unroll
    for (int i = 0; i < 4; i++) {
        int r = lrr + i * 32;
        CP_ASYNC16(smem_u32(&As[0][r][lsc]), Abase + (size_t)r * K + lgc);
        CP_ASYNC16(smem_u32(&Bs[0][r][lsc]), Bbase + (size_t)r * K + lgc);
    }
    CP_COMMIT();

    for (int it = 0; it < ktiles; it++) {
        int cur = it & 1;
        CP_WAIT0();
        __syncthreads();
        // prefetch tile it+1 into the other stage (its readers all passed the sync)
        if (it + 1 < ktiles) {
            int k0 = (it + 1) << 6;
            #pragma unroll
            for (int i = 0; i < 4; i++) {
                int r = lrr + i * 32;
                CP_ASYNC16(smem_u32(&As[cur ^ 1][r][lsc]), Abase + (size_t)r * K + k0 + lgc);
                CP_ASYNC16(smem_u32(&Bs[cur ^ 1][r][lsc]), Bbase + (size_t)r * K + k0 + lgc);
            }
            CP_COMMIT();
        }

        #pragma unroll
        for (int ks = 0; ks < 4; ks++) {
            int cbase = (ks >> 1) * 40 + (ks & 1) * 16;   // slab*40 + within-slab 0/16
            uint32_t a[2][4], b[8][2];
            #pragma unroll
            for (int mt = 0; mt < 2; mt++) {
                uint32_t addr = smem_u32(&As[cur][wm + mt * 16 + a_row][cbase + a_col]);
                LDSM_X4(a[mt][0], a[mt][1], a[mt][2], a[mt][3], addr);
            }
            #pragma unroll
            for (int ntp = 0; ntp < 8; ntp += 2) {
                uint32_t addr = smem_u32(&Bs[cur][wn + ntp * 8 + b_row][cbase + b_col]);
                LDSM_X4(b[ntp][0], b[ntp][1], b[ntp + 1][0], b[ntp + 1][1], addr);
            }
            #pragma unroll
            for (int mt = 0; mt < 2; mt++)
                #pragma unroll
                for (int nt = 0; nt < 8; nt++)
                    mma_f16(acc[mt][nt], a[mt], b[nt]);
        }
        __syncthreads();
    }

    #pragma unroll
    for (int mt = 0; mt < 2; mt++) {
        int r0 = bm + wm + mt * 16 + g;
        #pragma unroll
        for (int nt = 0; nt < 8; nt++) {
            int c0 = bn + wn + nt * 8 + tg * 2;
            float bz0 = bias[c0], bz1 = bias[c0 + 1];
            if (HALF_OUT) {
                __half* C = (__half*)Cv;
                *reinterpret_cast<__half2*>(C + (size_t)r0 * N + c0) =
                    __floats2half2_rn(acc[mt][nt][0] + bz0, acc[mt][nt][1] + bz1);
                *reinterpret_cast<__half2*>(C + (size_t)(r0 + 8) * N + c0) =
                    __floats2half2_rn(acc[mt][nt][2] + bz0, acc[mt][nt][3] + bz1);
            } else {
                float* C = (float*)Cv;
                C[(size_t)r0 * N + c0]           = acc[mt][nt][0] + bz0;
                C[(size_t)r0 * N + c0 + 1]       = acc[mt][nt][1] + bz1;
                C[(size_t)(r0 + 8) * N + c0]     = acc[mt][nt][2] + bz0;
                C[(size_t)(r0 + 8) * N + c0 + 1] = acc[mt][nt][3] + bz1;
            }
        }
    }
}

// ------------------------- Flash attention (causal, fp16 mma) -------------------------
// (unchanged from R14: double-buffered 128-token tiles, ldmatrix K / ldmatrix.trans V)
__global__ __launch_bounds__(256, 2) void attn_kernel(const __half* __restrict__ qkv,
                                                      __half* __restrict__ y) {
    __shared__ __half bufK[2][128][72];
    __shared__ __half bufV[2][128][72];
    int qt = gridDim.x - 1 - blockIdx.x;
    int h = blockIdx.y, b = blockIdx.z;
    int tid = threadIdx.x, lane = tid & 31, w = tid >> 5;
    int g = lane >> 2, tg = lane & 3;
    int q0 = qt * 128;
    int row0 = q0 + w * 16;
    const size_t rstr = (size_t)3 * NE;
    const __half* kbase = qkv + ((size_t)b * SEQT) * rstr + NE + h * HD;
    const __half* vbase = qkv + ((size_t)b * SEQT) * rstr + 2 * NE + h * HD;

    int krow = (lane & 7) + (lane >> 4) * 8;
    int kcol = ((lane >> 3) & 1) * 8;
    int vrow = (lane & 7) + ((lane >> 3) & 1) * 8;
    int vcol = (lane >> 4) * 8;
    int lr = tid >> 3, lc = (tid & 7) * 8;

    const __half2 sc2 = __float2half2_rn(0.125f);
    const __half* qbase = qkv + ((size_t)b * SEQT + row0) * rstr + h * HD;
    uint32_t qf[4][4];
    #pragma unroll
    for (int ks = 0; ks < 4; ks++) {
        int c = ks * 16 + tg * 2;
        __half2 v0 = __hmul2(*reinterpret_cast<const __half2*>(qbase + (size_t)g * rstr + c), sc2);
        __half2 v1 = __hmul2(*reinterpret_cast<const __half2*>(qbase + (size_t)(g + 8) * rstr + c), sc2);
        __half2 v2 = __hmul2(*reinterpret_cast<const __half2*>(qbase + (size_t)g * rstr + c + 8), sc2);
        __half2 v3 = __hmul2(*reinterpret_cast<const __half2*>(qbase + (size_t)(g + 8) * rstr + c + 8), sc2);
        qf[ks][0] = *reinterpret_cast<uint32_t*>(&v0);
        qf[ks][1] = *reinterpret_cast<uint32_t*>(&v1);
        qf[ks][2] = *reinterpret_cast<uint32_t*>(&v2);
        qf[ks][3] = *reinterpret_cast<uint32_t*>(&v3);
    }

    float O[8][4];
    #pragma unroll
    for (int dt = 0; dt < 8; dt++)
        #pragma unroll
        for (int i = 0; i < 4; i++) O[dt][i] = 0.f;
    float m0 = -1e30f, m1 = -1e30f, l0 = 0.f, l1 = 0.f;

    int ntile = qt + 1;
    {
        #pragma unroll
        for (int i = 0; i < 4; i++) {
            int r = lr + i * 32;
            CP_ASYNC16(smem_u32(&bufK[0][r][lc]), kbase + (size_t)r * rstr + lc);
            CP_ASYNC16(smem_u32(&bufV[0][r][lc]), vbase + (size_t)r * rstr + lc);
        }
        CP_COMMIT();
    }

    for (int kt = 0; kt < ntile; kt++) {
        int cur = kt & 1;
        if (kt + 1 < ntile) {
            int kb0 = (kt + 1) * 128;
            #pragma unroll
            for (int i = 0; i < 4; i++) {
                int r = lr + i * 32;
                CP_ASYNC16(smem_u32(&bufK[cur ^ 1][r][lc]), kbase + (size_t)(kb0 + r) * rstr + lc);
                CP_ASYNC16(smem_u32(&bufV[cur ^ 1][r][lc]), vbase + (size_t)(kb0 + r) * rstr + lc);
            }
            CP_COMMIT();
            CP_WAIT1();
        } else {
            CP_WAIT0();
        }
        __syncthreads();

        int kb0 = kt * 128;
        #pragma unroll
        for (int hf = 0; hf < 2; hf++) {
            int kb = kb0 + hf * 64;
            if (kb > row0 + 15) break;
            int ro = hf * 64;

            float S[8][4];
            #pragma unroll
            for (int nt = 0; nt < 8; nt++)
                #pragma unroll
                for (int i = 0; i < 4; i++) S[nt][i] = 0.f;
            #pragma unroll
            for (int ks = 0; ks < 4; ks++) {
                #pragma unroll
                for (int ntp = 0; ntp < 8; ntp += 2) {
                    uint32_t bk[2][2];
                    uint32_t addr = smem_u32(&bufK[cur][ro + ntp * 8 + krow][ks * 16 + kcol]);
                    LDSM_X4(bk[0][0], bk[0][1], bk[1][0], bk[1][1], addr);
                    mma_f16(S[ntp],     qf[ks], bk[0]);
                    mma_f16(S[ntp + 1], qf[ks], bk[1]);
                }
            }

            if (kb + 63 > row0) {
                int r = row0 + g;
                #pragma unroll
                for (int nt = 0; nt < 8; nt++) {
                    int c = kb + nt * 8 + tg * 2;
                    if (c     > r)     S[nt][0] = -1e30f;
                    if (c + 1 > r)     S[nt][1] = -1e30f;
                    if (c     > r + 8) S[nt][2] = -1e30f;
                    if (c + 1 > r + 8) S[nt][3] = -1e30f;
                }
            }

            float mx0 = -1e30f, mx1 = -1e30f;
            #pragma unroll
            for (int nt = 0; nt < 8; nt++) {
                mx0 = fmaxf(mx0, fmaxf(S[nt][0], S[nt][1]));
                mx1 = fmaxf(mx1, fmaxf(S[nt][2], S[nt][3]));
            }
            #pragma unroll
            for (int o = 1; o <= 2; o <<= 1) {
                mx0 = fmaxf(mx0, __shfl_xor_sync(0xffffffffu, mx0, o));
                mx1 = fmaxf(mx1, __shfl_xor_sync(0xffffffffu, mx1, o));
            }
            float nm0 = fmaxf(m0, mx0), nm1 = fmaxf(m1, mx1);
            float al0 = __expf(m0 - nm0), al1 = __expf(m1 - nm1);
            float rs0 = 0.f, rs1 = 0.f;
            #pragma unroll
            for (int nt = 0; nt < 8; nt++) {
                S[nt][0] = __expf(S[nt][0] - nm0); rs0 += S[nt][0];
                S[nt][1] = __expf(S[nt][1] - nm0); rs0 += S[nt][1];
                S[nt][2] = __expf(S[nt][2] - nm1); rs1 += S[nt][2];
                S[nt][3] = __expf(S[nt][3] - nm1); rs1 += S[nt][3];
            }
            #pragma unroll
            for (int o = 1; o <= 2; o <<= 1) {
                rs0 += __shfl_xor_sync(0xffffffffu, rs0, o);
                rs1 += __shfl_xor_sync(0xffffffffu, rs1, o);
            }
            l0 = l0 * al0 + rs0; l1 = l1 * al1 + rs1;
            m0 = nm0; m1 = nm1;
            #pragma unroll
            for (int dt = 0; dt < 8; dt++) {
                O[dt][0] *= al0; O[dt][1] *= al0; O[dt][2] *= al1; O[dt][3] *= al1;
            }

            #pragma unroll
            for (int ks = 0; ks < 4; ks++) {
                __half2 p0 = __floats2half2_rn(S[2 * ks][0],     S[2 * ks][1]);
                __half2 p1 = __floats2half2_rn(S[2 * ks][2],     S[2 * ks][3]);
                __half2 p2 = __floats2half2_rn(S[2 * ks + 1][0], S[2 * ks + 1][1]);
                __half2 p3 = __floats2half2_rn(S[2 * ks + 1][2], S[2 * ks + 1][3]);
                uint32_t pa[4];
                pa[0] = *reinterpret_cast<uint32_t*>(&p0);
                pa[1] = *reinterpret_cast<uint32_t*>(&p1);
                pa[2] = *reinterpret_cast<uint32_t*>(&p2);
                pa[3] = *reinterpret_cast<uint32_t*>(&p3);
                #pragma unroll
                for (int dtp = 0; dtp < 8; dtp += 2) {
                    uint32_t bv[2][2];
                    uint32_t addr = smem_u32(&bufV[cur][ro + ks * 16 + vrow][dtp * 8 + vcol]);
                    LDSM_X4_T(bv[0][0], bv[0][1], bv[1][0], bv[1][1], addr);
                    mma_f16(O[dtp],     pa, bv[0]);
                    mma_f16(O[dtp + 1], pa, bv[1]);
                }
            }
        }
        __syncthreads();
    }

    float il0 = 1.f / l0, il1 = 1.f / l1;
    int r = row0 + g;
    __half* yb  = y + ((size_t)b * SEQT + r) * NE + h * HD;
    __half* yb8 = y + ((size_t)b * SEQT + r + 8) * NE + h * HD;
    #pragma unroll
    for (int dt = 0; dt < 8; dt++) {
        int c = dt * 8 + tg * 2;
        *reinterpret_cast<__half2*>(yb + c)  = __floats2half2_rn(O[dt][0] * il0, O[dt][1] * il0);
        *reinterpret_cast<__half2*>(yb8 + c) = __floats2half2_rn(O[dt][2] * il1, O[dt][3] * il1);
    }
}

// ------------------------- launch -------------------------
extern "C" void kernel_launch(void* const* d_in, const int* in_sizes, int n_in,
                              void* d_out, int out_size) {
    const float* x      = (const float*)d_in[0];
    const float* ln_w   = (const float*)d_in[1];
    const float* ln_b   = (const float*)d_in[2];
    const float* W_attn = (const float*)d_in[3];
    const float* b_attn = (const float*)d_in[4];
    const float* W_proj = (const float*)d_in[5];
    const float* b_proj = (const float*)d_in[6];
    float* out = (float*)d_out;

    __half *h, *qkv, *y, *wta, *wtp;
    cudaGetSymbolAddress((void**)&h,   g_h);
    cudaGetSymbolAddress((void**)&qkv, g_qkv);
    cudaGetSymbolAddress((void**)&y,   g_y);
    cudaGetSymbolAddress((void**)&wta, g_wta);
    cudaGetSymbolAddress((void**)&wtp, g_wtp);

    transpose_w<<<dim3(3 * NE / 32, CIN / 32), dim3(32, 8)>>>(W_attn, wta, CIN, 3 * NE);
    transpose_w<<<dim3(NE / 32, NE / 32),      dim3(32, 8)>>>(W_proj, wtp, NE, NE);
    ln_kernel<<<ROWS, 256>>>(x, ln_w, ln_b, h);
    gemm_f16<true><<<dim3(3 * NE / 128, ROWS / 128), 256>>>(h, wta, b_attn, qkv, ROWS, 3 * NE, CIN);
    attn_kernel<<<dim3(SEQT / 128, NH, BATCH), 256>>>(qkv, y);
    gemm_f16<false><<<dim3(NE / 128, ROWS / 128), 256>>>(y, wtp, b_proj, out, ROWS, NE, NE);
}

// round 16
// speedup vs baseline: 1.2103x; 1.2103x over previous
#include <cuda_runtime.h>
#include <cuda_fp16.h>
#include <cstdint>
#include <cstddef>

#define BATCH 4
#define SEQT  2048
#define CIN   1152
#define NE    1024
#define NH    16
#define HD    64
#define ROWS  (BATCH*SEQT)   // 8192

// ---- scratch (no allocations allowed) ----
__device__ __half g_h[(size_t)ROWS * CIN];
__device__ __half g_qkv[(size_t)ROWS * 3 * NE];
__device__ __half g_y[(size_t)ROWS * NE];
__device__ __half g_wta[(size_t)3 * NE * CIN];
__device__ __half g_wtp[(size_t)NE * NE];

__device__ __forceinline__ void mma_f16(float c[4], const uint32_t a[4], const uint32_t b[2]) {
    asm volatile(
        "mma.sync.aligned.m16n8k16.row.col.f32.f16.f16.f32 "
        "{%0,%1,%2,%3}, {%4,%5,%6,%7}, {%8,%9}, {%0,%1,%2,%3};\n"
        : "+f"(c[0]), "+f"(c[1]), "+f"(c[2]), "+f"(c[3])
        : "r"(a[0]), "r"(a[1]), "r"(a[2]), "r"(a[3]), "r"(b[0]), "r"(b[1]));
}

__device__ __forceinline__ uint32_t smem_u32(const void* p) {
    return (uint32_t)__cvta_generic_to_shared(p);
}
#define CP_ASYNC16(dst, src) \
    asm volatile("cp.async.cg.shared.global [%0], [%1], 16;\n" :: "r"(dst), "l"(src))
#define CP_COMMIT() asm volatile("cp.async.commit_group;\n")
#define CP_WAIT1()  asm volatile("cp.async.wait_group 1;\n")
#define CP_WAIT0()  asm volatile("cp.async.wait_group 0;\n")
#define LDSM_X4(r0, r1, r2, r3, addr) \
    asm volatile("ldmatrix.sync.aligned.m8n8.x4.shared.b16 {%0,%1,%2,%3}, [%4];" \
                 : "=r"(r0), "=r"(r1), "=r"(r2), "=r"(r3) : "r"(addr))
#define LDSM_X4_T(r0, r1, r2, r3, addr) \
    asm volatile("ldmatrix.sync.aligned.m8n8.x4.trans.shared.b16 {%0,%1,%2,%3}, [%4];" \
                 : "=r"(r0), "=r"(r1), "=r"(r2), "=r"(r3) : "r"(addr))

// ---------------- weight transpose + half convert ----------------
__global__ void transpose_w(const float* __restrict__ W, __half* __restrict__ wT, int K, int N) {
    __shared__ float t[32][33];
    int n0 = blockIdx.x * 32, k0 = blockIdx.y * 32;
    #pragma unroll
    for (int i = threadIdx.y; i < 32; i += 8)
        t[i][threadIdx.x] = W[(size_t)(k0 + i) * N + n0 + threadIdx.x];
    __syncthreads();
    #pragma unroll
    for (int i = threadIdx.y; i < 32; i += 8)
        wT[(size_t)(n0 + i) * K + k0 + threadIdx.x] = __float2half_rn(t[threadIdx.x][i]);
}

// ------------------------- LayerNorm (single-pass, float4-resident) -------------------------
// 288 threads/block, one row/block: each thread owns exactly one float4 (288*4=1152).
__global__ __launch_bounds__(288) void ln_kernel(const float* __restrict__ x,
                                                 const float* __restrict__ w,
                                                 const float* __restrict__ bb,
                                                 __half* __restrict__ h) {
    int row = blockIdx.x;
    int tid = threadIdx.x;                 // 0..287
    const float4 v = ((const float4*)(x + (size_t)row * CIN))[tid];
    float s1 = v.x + v.y + v.z + v.w;
    float s2 = v.x * v.x + v.y * v.y + v.z * v.z + v.w * v.w;
    #pragma unroll
    for (int o = 16; o; o >>= 1) {
        s1 += __shfl_xor_sync(0xffffffffu, s1, o);
        s2 += __shfl_xor_sync(0xffffffffu, s2, o);
    }
    __shared__ float sh1[9], sh2[9];
    int wid = tid >> 5, lane = tid & 31;
    if (lane == 0) { sh1[wid] = s1; sh2[wid] = s2; }
    __syncthreads();
    float S1 = 0.f, S2 = 0.f;
    #pragma unroll
    for (int i = 0; i < 9; i++) { S1 += sh1[i]; S2 += sh2[i]; }
    float mean = S1 * (1.f / CIN);
    float var  = S2 * (1.f / CIN) - mean * mean;
    float inv  = rsqrtf(var + 1e-5f);
    const float4 ww = ((const float4*)w)[tid];
    const float4 bz = ((const float4*)bb)[tid];
    __half2* hr = (__half2*)(h + (size_t)row * CIN);
    hr[tid * 2]     = __floats2half2_rn((v.x - mean) * inv * ww.x + bz.x,
                                        (v.y - mean) * inv * ww.y + bz.y);
    hr[tid * 2 + 1] = __floats2half2_rn((v.z - mean) * inv * ww.z + bz.z,
                                        (v.w - mean) * inv * ww.w + bz.w);
}

// ------------------------- fp16 GEMM: C = A@Bt^T + bias -------------------------
// 3-stage cp.async, 1 sync/iter, ldmatrix fragments. (R14-validated: 189us QKV)
template<bool HALF_OUT>
__global__ __launch_bounds__(256) void gemm_f16(
        const __half* __restrict__ A, const __half* __restrict__ Bt,
        const float* __restrict__ bias, void* __restrict__ Cv,
        int M, int N, int K) {
    __shared__ __half As[3][128][40];
    __shared__ __half Bs[3][128][40];
    int tid = threadIdx.x;
    int lane = tid & 31, wid = tid >> 5;
    int wm = (wid & 3) * 32, wn = (wid >> 2) * 64;
    int bm = blockIdx.y * 128, bn = blockIdx.x * 128;
    int g = lane >> 2, tg = lane & 3;

    float acc[2][8][4];
    #pragma unroll
    for (int mt = 0; mt < 2; mt++)
        #pragma unroll
        for (int nt = 0; nt < 8; nt++)
            #pragma unroll
            for (int i = 0; i < 4; i++) acc[mt][nt][i] = 0.f;

    const __half* Abase = A + (size_t)bm * K;
    const __half* Bbase = Bt + (size_t)bn * K;
    int ktiles = K >> 5;

    int a_row = (lane & 7) + ((lane >> 3) & 1) * 8;
    int a_col = (lane >> 4) * 8;
    int b_row = (lane & 7) + (lane >> 4) * 8;
    int b_col = ((lane >> 3) & 1) * 8;

    int lr = tid >> 2, lc = (tid & 3) * 8;
    int lr2 = (tid + 256) >> 2, lc2 = ((tid + 256) & 3) * 8;

    #pragma unroll
    for (int s = 0; s < 2; s++) {
        int k0 = s << 5;
        CP_ASYNC16(smem_u32(&As[s][lr][lc]),  Abase + (size_t)lr * K + k0 + lc);
        CP_ASYNC16(smem_u32(&Bs[s][lr][lc]),  Bbase + (size_t)lr * K + k0 + lc);
        CP_ASYNC16(smem_u32(&As[s][lr2][lc2]), Abase + (size_t)lr2 * K + k0 + lc2);
        CP_ASYNC16(smem_u32(&Bs[s][lr2][lc2]), Bbase + (size_t)lr2 * K + k0 + lc2);
        CP_COMMIT();
    }

    for (int it = 0; it < ktiles; it++) {
        CP_WAIT1();
        __syncthreads();
        int cur = it % 3;

        #pragma unroll
        for (int ks = 0; ks < 2; ks++) {
            uint32_t a[2][4], b[8][2];
            #pragma unroll
            for (int mt = 0; mt < 2; mt++) {
                uint32_t addr = smem_u32(&As[cur][wm + mt * 16 + a_row][ks * 16 + a_col]);
                LDSM_X4(a[mt][0], a[mt][1], a[mt][2], a[mt][3], addr);
            }
            #pragma unroll
            for (int ntp = 0; ntp < 8; ntp += 2) {
                uint32_t addr = smem_u32(&Bs[cur][wn + ntp * 8 + b_row][ks * 16 + b_col]);
                LDSM_X4(b[ntp][0], b[ntp][1], b[ntp + 1][0], b[ntp + 1][1], addr);
            }
            #pragma unroll
            for (int mt = 0; mt < 2; mt++)
                #pragma unroll
                for (int nt = 0; nt < 8; nt++)
                    mma_f16(acc[mt][nt], a[mt], b[nt]);
        }

        int nt_ = it + 2;
        if (nt_ < ktiles) {
            int s = nt_ % 3, k0 = nt_ << 5;
            CP_ASYNC16(smem_u32(&As[s][lr][lc]),  Abase + (size_t)lr * K + k0 + lc);
            CP_ASYNC16(smem_u32(&Bs[s][lr][lc]),  Bbase + (size_t)lr * K + k0 + lc);
            CP_ASYNC16(smem_u32(&As[s][lr2][lc2]), Abase + (size_t)lr2 * K + k0 + lc2);
            CP_ASYNC16(smem_u32(&Bs[s][lr2][lc2]), Bbase + (size_t)lr2 * K + k0 + lc2);
        }
        CP_COMMIT();
    }

    #pragma unroll
    for (int mt = 0; mt < 2; mt++) {
        int r0 = bm + wm + mt * 16 + g;
        #pragma unroll
        for (int nt = 0; nt < 8; nt++) {
            int c0 = bn + wn + nt * 8 + tg * 2;
            float bz0 = bias[c0], bz1 = bias[c0 + 1];
            if (HALF_OUT) {
                __half* C = (__half*)Cv;
                *reinterpret_cast<__half2*>(C + (size_t)r0 * N + c0) =
                    __floats2half2_rn(acc[mt][nt][0] + bz0, acc[mt][nt][1] + bz1);
                *reinterpret_cast<__half2*>(C + (size_t)(r0 + 8) * N + c0) =
                    __floats2half2_rn(acc[mt][nt][2] + bz0, acc[mt][nt][3] + bz1);
            } else {
                float* C = (float*)Cv;
                C[(size_t)r0 * N + c0]           = acc[mt][nt][0] + bz0;
                C[(size_t)r0 * N + c0 + 1]       = acc[mt][nt][1] + bz1;
                C[(size_t)(r0 + 8) * N + c0]     = acc[mt][nt][2] + bz0;
                C[(size_t)(r0 + 8) * N + c0 + 1] = acc[mt][nt][3] + bz1;
            }
        }
    }
}

// ------------------------- Flash attention (causal, fp16 mma) -------------------------
// (R14-validated: double-buffered 128-token tiles, ldmatrix K / ldmatrix.trans V)
__global__ __launch_bounds__(256, 2) void attn_kernel(const __half* __restrict__ qkv,
                                                      __half* __restrict__ y) {
    __shared__ __half bufK[2][128][72];
    __shared__ __half bufV[2][128][72];
    int qt = gridDim.x - 1 - blockIdx.x;
    int h = blockIdx.y, b = blockIdx.z;
    int tid = threadIdx.x, lane = tid & 31, w = tid >> 5;
    int g = lane >> 2, tg = lane & 3;
    int q0 = qt * 128;
    int row0 = q0 + w * 16;
    const size_t rstr = (size_t)3 * NE;
    const __half* kbase = qkv + ((size_t)b * SEQT) * rstr + NE + h * HD;
    const __half* vbase = qkv + ((size_t)b * SEQT) * rstr + 2 * NE + h * HD;

    int krow = (lane & 7) + (lane >> 4) * 8;
    int kcol = ((lane >> 3) & 1) * 8;
    int vrow = (lane & 7) + ((lane >> 3) & 1) * 8;
    int vcol = (lane >> 4) * 8;
    int lr = tid >> 3, lc = (tid & 7) * 8;

    const __half2 sc2 = __float2half2_rn(0.125f);
    const __half* qbase = qkv + ((size_t)b * SEQT + row0) * rstr + h * HD;
    uint32_t qf[4][4];
    #pragma unroll
    for (int ks = 0; ks < 4; ks++) {
        int c = ks * 16 + tg * 2;
        __half2 v0 = __hmul2(*reinterpret_cast<const __half2*>(qbase + (size_t)g * rstr + c), sc2);
        __half2 v1 = __hmul2(*reinterpret_cast<const __half2*>(qbase + (size_t)(g + 8) * rstr + c), sc2);
        __half2 v2 = __hmul2(*reinterpret_cast<const __half2*>(qbase + (size_t)g * rstr + c + 8), sc2);
        __half2 v3 = __hmul2(*reinterpret_cast<const __half2*>(qbase + (size_t)(g + 8) * rstr + c + 8), sc2);
        qf[ks][0] = *reinterpret_cast<uint32_t*>(&v0);
        qf[ks][1] = *reinterpret_cast<uint32_t*>(&v1);
        qf[ks][2] = *reinterpret_cast<uint32_t*>(&v2);
        qf[ks][3] = *reinterpret_cast<uint32_t*>(&v3);
    }

    float O[8][4];
    #pragma unroll
    for (int dt = 0; dt < 8; dt++)
        #pragma unroll
        for (int i = 0; i < 4; i++) O[dt][i] = 0.f;
    float m0 = -1e30f, m1 = -1e30f, l0 = 0.f, l1 = 0.f;

    int ntile = qt + 1;
    {
        #pragma unroll
        for (int i = 0; i < 4; i++) {
            int r = lr + i * 32;
            CP_ASYNC16(smem_u32(&bufK[0][r][lc]), kbase + (size_t)r * rstr + lc);
            CP_ASYNC16(smem_u32(&bufV[0][r][lc]), vbase + (size_t)r * rstr + lc);
        }
        CP_COMMIT();
    }

    for (int kt = 0; kt < ntile; kt++) {
        int cur = kt & 1;
        if (kt + 1 < ntile) {
            int kb0 = (kt + 1) * 128;
            #pragma unroll
            for (int i = 0; i < 4; i++) {
                int r = lr + i * 32;
                CP_ASYNC16(smem_u32(&bufK[cur ^ 1][r][lc]), kbase + (size_t)(kb0 + r) * rstr + lc);
                CP_ASYNC16(smem_u32(&bufV[cur ^ 1][r][lc]), vbase + (size_t)(kb0 + r) * rstr + lc);
            }
            CP_COMMIT();
            CP_WAIT1();
        } else {
            CP_WAIT0();
        }
        __syncthreads();

        int kb0 = kt * 128;
        #pragma unroll
        for (int hf = 0; hf < 2; hf++) {
            int kb = kb0 + hf * 64;
            if (kb > row0 + 15) break;
            int ro = hf * 64;

            float S[8][4];
            #pragma unroll
            for (int nt = 0; nt < 8; nt++)
                #pragma unroll
                for (int i = 0; i < 4; i++) S[nt][i] = 0.f;
            #pragma unroll
            for (int ks = 0; ks < 4; ks++) {
                #pragma unroll
                for (int ntp = 0; ntp < 8; ntp += 2) {
                    uint32_t bk[2][2];
                    uint32_t addr = smem_u32(&bufK[cur][ro + ntp * 8 + krow][ks * 16 + kcol]);
                    LDSM_X4(bk[0][0], bk[0][1], bk[1][0], bk[1][1], addr);
                    mma_f16(S[ntp],     qf[ks], bk[0]);
                    mma_f16(S[ntp + 1], qf[ks], bk[1]);
                }
            }

            if (kb + 63 > row0) {
                int r = row0 + g;
                #pragma unroll
                for (int nt = 0; nt < 8; nt++) {
                    int c = kb + nt * 8 + tg * 2;
                    if (c     > r)     S[nt][0] = -1e30f;
                    if (c + 1 > r)     S[nt][1] = -1e30f;
                    if (c     > r + 8) S[nt][2] = -1e30f;
                    if (c + 1 > r + 8) S[nt][3] = -1e30f;
                }
            }

            float mx0 = -1e30f, mx1 = -1e30f;
            #pragma unroll
            for (int nt = 0; nt < 8; nt++) {
                mx0 = fmaxf(mx0, fmaxf(S[nt][0], S[nt][1]));
                mx1 = fmaxf(mx1, fmaxf(S[nt][2], S[nt][3]));
            }
            #pragma unroll
            for (int o = 1; o <= 2; o <<= 1) {
                mx0 = fmaxf(mx0, __shfl_xor_sync(0xffffffffu, mx0, o));
                mx1 = fmaxf(mx1, __shfl_xor_sync(0xffffffffu, mx1, o));
            }
            float nm0 = fmaxf(m0, mx0), nm1 = fmaxf(m1, mx1);
            float al0 = __expf(m0 - nm0), al1 = __expf(m1 - nm1);
            float rs0 = 0.f, rs1 = 0.f;
            #pragma unroll
            for (int nt = 0; nt < 8; nt++) {
                S[nt][0] = __expf(S[nt][0] - nm0); rs0 += S[nt][0];
                S[nt][1] = __expf(S[nt][1] - nm0); rs0 += S[nt][1];
                S[nt][2] = __expf(S[nt][2] - nm1); rs1 += S[nt][2];
                S[nt][3] = __expf(S[nt][3] - nm1); rs1 += S[nt][3];
            }
            #pragma unroll
            for (int o = 1; o <= 2; o <<= 1) {
                rs0 += __shfl_xor_sync(0xffffffffu, rs0, o);
                rs1 += __shfl_xor_sync(0xffffffffu, rs1, o);
            }
            l0 = l0 * al0 + rs0; l1 = l1 * al1 + rs1;
            m0 = nm0; m1 = nm1;
            #pragma unroll
            for (int dt = 0; dt < 8; dt++) {
                O[dt][0] *= al0; O[dt][1] *= al0; O[dt][2] *= al1; O[dt][3] *= al1;
            }

            #pragma unroll
            for (int ks = 0; ks < 4; ks++) {
                __half2 p0 = __floats2half2_rn(S[2 * ks][0],     S[2 * ks][1]);
                __half2 p1 = __floats2half2_rn(S[2 * ks][2],     S[2 * ks][3]);
                __half2 p2 = __floats2half2_rn(S[2 * ks + 1][0], S[2 * ks + 1][1]);
                __half2 p3 = __floats2half2_rn(S[2 * ks + 1][2], S[2 * ks + 1][3]);
                uint32_t pa[4];
                pa[0] = *reinterpret_cast<uint32_t*>(&p0);
                pa[1] = *reinterpret_cast<uint32_t*>(&p1);
                pa[2] = *reinterpret_cast<uint32_t*>(&p2);
                pa[3] = *reinterpret_cast<uint32_t*>(&p3);
                #pragma unroll
                for (int dtp = 0; dtp < 8; dtp += 2) {
                    uint32_t bv[2][2];
                    uint32_t addr = smem_u32(&bufV[cur][ro + ks * 16 + vrow][dtp * 8 + vcol]);
                    LDSM_X4_T(bv[0][0], bv[0][1], bv[1][0], bv[1][1], addr);
                    mma_f16(O[dtp],     pa, bv[0]);
                    mma_f16(O[dtp + 1], pa, bv[1]);
                }
            }
        }
        __syncthreads();
    }

    float il0 = 1.f / l0, il1 = 1.f / l1;
    int r = row0 + g;
    __half* yb  = y + ((size_t)b * SEQT + r) * NE + h * HD;
    __half* yb8 = y + ((size_t)b * SEQT + r + 8) * NE + h * HD;
    #pragma unroll
    for (int dt = 0; dt < 8; dt++) {
        int c = dt * 8 + tg * 2;
        *reinterpret_cast<__half2*>(yb + c)  = __floats2half2_rn(O[dt][0] * il0, O[dt][1] * il0);
        *reinterpret_cast<__half2*>(yb8 + c) = __floats2half2_rn(O[dt][2] * il1, O[dt][3] * il1);
    }
}

// ------------------------- launch -------------------------
extern "C" void kernel_launch(void* const* d_in, const int* in_sizes, int n_in,
                              void* d_out, int out_size) {
    const float* x      = (const float*)d_in[0];
    const float* ln_w   = (const float*)d_in[1];
    const float* ln_b   = (const float*)d_in[2];
    const float* W_attn = (const float*)d_in[3];
    const float* b_attn = (const float*)d_in[4];
    const float* W_proj = (const float*)d_in[5];
    const float* b_proj = (const float*)d_in[6];
    float* out = (float*)d_out;

    __half *h, *qkv, *y, *wta, *wtp;
    cudaGetSymbolAddress((void**)&h,   g_h);
    cudaGetSymbolAddress((void**)&qkv, g_qkv);
    cudaGetSymbolAddress((void**)&y,   g_y);
    cudaGetSymbolAddress((void**)&wta, g_wta);
    cudaGetSymbolAddress((void**)&wtp, g_wtp);

    transpose_w<<<dim3(3 * NE / 32, CIN / 32), dim3(32, 8)>>>(W_attn, wta, CIN, 3 * NE);
    transpose_w<<<dim3(NE / 32, NE / 32),      dim3(32, 8)>>>(W_proj, wtp, NE, NE);
    ln_kernel<<<ROWS, 288>>>(x, ln_w, ln_b, h);
    gemm_f16<true><<<dim3(3 * NE / 128, ROWS / 128), 256>>>(h, wta, b_attn, qkv, ROWS, 3 * NE, CIN);
    attn_kernel<<<dim3(SEQT / 128, NH, BATCH), 256>>>(qkv, y);
    gemm_f16<false><<<dim3(NE / 128, ROWS / 128), 256>>>(y, wtp, b_proj, out, ROWS, NE, NE);
}